// round 8
// baseline (speedup 1.0000x reference)
#include <cuda_runtime.h>
#include <cuda_bf16.h>
#include <cstdint>

// Problem constants (GCN_71124658421835)
#define NMAX  50000
#define EMAX  1600000
#define FIN   256
#define HID   64
#define FOUT  128

typedef unsigned long long u64;

// Scratch (no allocation allowed -> __device__ globals)
__device__ __align__(16) float g_dinv[NMAX];
__device__ __align__(16) float g_hs1 [NMAX * HID];     // (x@W1)*dinv
__device__ __align__(16) float g_hh1 [NMAX * HID];     // relu(gcn1)*dinv
__device__ __align__(16) float g_hh2 [NMAX * HID];     // A_hat @ h
__device__ int g_hist[NMAX];
__device__ int g_off [NMAX + 1];
__device__ int g_cur [NMAX];
__device__ int g_srt [EMAX];                           // src sorted by dst (CSR adj)
__device__ int g_part[256];
__device__ int g_poff[256];

// ---------------------------------------------------------------------------
// f32x2 helpers (Blackwell packed fp32 pipe)
// ---------------------------------------------------------------------------
__device__ __forceinline__ u64 fma2(u64 a, u64 b, u64 c) {
    u64 d;
    asm("fma.rn.f32x2 %0, %1, %2, %3;" : "=l"(d) : "l"(a), "l"(b), "l"(c));
    return d;
}
__device__ __forceinline__ float2 unpack2(u64 v) {
    float2 r;
    asm("mov.b64 {%0, %1}, %2;" : "=f"(r.x), "=f"(r.y) : "l"(v));
    return r;
}

// ---------------------------------------------------------------------------
// Degree histogram
// ---------------------------------------------------------------------------
__global__ void k_hist4(const int4* __restrict__ dst4, int* hist, int E4) {
    int i = blockIdx.x * blockDim.x + threadIdx.x;
    if (i < E4) {
        int4 d = __ldg(&dst4[i]);
        atomicAdd(&hist[d.x], 1);
        atomicAdd(&hist[d.y], 1);
        atomicAdd(&hist[d.z], 1);
        atomicAdd(&hist[d.w], 1);
    }
}

__global__ void k_hist1(const int* __restrict__ dst, int* hist, int E) {
    int i = blockIdx.x * blockDim.x + threadIdx.x;
    if (i < E) atomicAdd(&hist[dst[i]], 1);
}

// ---------------------------------------------------------------------------
// 3-phase parallel exclusive scan over hist (N <= 256*256), emits off/cur/dinv.
// ---------------------------------------------------------------------------
__global__ void k_scanA(const int* __restrict__ hist, int* __restrict__ part, int n) {
    __shared__ int s[256];
    int t = threadIdx.x, i = blockIdx.x * 256 + t;
    s[t] = (i < n) ? hist[i] : 0;
    __syncthreads();
    for (int d = 128; d > 0; d >>= 1) {
        if (t < d) s[t] += s[t + d];
        __syncthreads();
    }
    if (t == 0) part[blockIdx.x] = s[0];
}

__global__ void k_scanB(const int* __restrict__ part, int* __restrict__ poff, int nb) {
    __shared__ int s[256];
    int t = threadIdx.x;
    int v = (t < nb) ? part[t] : 0;
    s[t] = v;
    __syncthreads();
    for (int d = 1; d < 256; d <<= 1) {
        int x = (t >= d) ? s[t - d] : 0;
        __syncthreads();
        s[t] += x;
        __syncthreads();
    }
    if (t < nb) poff[t] = s[t] - v;          // exclusive
}

__global__ void k_scanC(const int* __restrict__ hist, const int* __restrict__ poff,
                        int* __restrict__ off, int* __restrict__ cur,
                        float* __restrict__ dinv, int n)
{
    __shared__ int s[256];
    int t = threadIdx.x, i = blockIdx.x * 256 + t;
    int v = (i < n) ? hist[i] : 0;
    s[t] = v;
    __syncthreads();
    for (int d = 1; d < 256; d <<= 1) {
        int x = (t >= d) ? s[t - d] : 0;
        __syncthreads();
        s[t] += x;
        __syncthreads();
    }
    int base = poff[blockIdx.x];
    int excl = base + s[t] - v;
    if (i < n) {
        off[i]  = excl;
        cur[i]  = excl;
        dinv[i] = rsqrtf((float)v + 1.0f);   // +1 self loop
    }
    if (i == n - 1) off[n] = excl + v;
}

// Fallback single-block scan (only if N > 65536)
__global__ void k_scan1b(const int* __restrict__ hist, int* __restrict__ off,
                         int* __restrict__ cur, float* __restrict__ dinv, int n)
{
    __shared__ int sums[1024];
    const int t = threadIdx.x;
    const int chunk = (n + 1023) >> 10;
    const int lo = t * chunk;
    const int hi = min(lo + chunk, n);
    int s = 0;
    for (int i = lo; i < hi; i++) s += hist[i];
    sums[t] = s;
    __syncthreads();
    for (int d = 1; d < 1024; d <<= 1) {
        int v = (t >= d) ? sums[t - d] : 0;
        __syncthreads();
        sums[t] += v;
        __syncthreads();
    }
    int run = (t == 0) ? 0 : sums[t - 1];
    for (int i = lo; i < hi; i++) {
        int c = hist[i];
        off[i] = run; cur[i] = run;
        dinv[i] = rsqrtf((float)c + 1.0f);
        run += c;
    }
    if (t == 1023) off[n] = sums[1023];
}

// ---------------------------------------------------------------------------
// Packed-f32x2 GEMM body. 8x8 per-thread tile = 4 M-pairs x 8 cols.
// A[M,K] row-major, B[K,N] row-major, THREADS = 128, BM=128, BN=64, BK=32.
// Epilogue: DOSCALE -> *dinv[row]; DOBIAS -> +bias[col].
// ---------------------------------------------------------------------------
template<int BM, int BN, int BK, bool DOSCALE, bool DOBIAS>
__device__ __forceinline__ void gemm_body(const float* __restrict__ A,
                                          const float* __restrict__ B,
                                          const float* __restrict__ dinv,
                                          const float* __restrict__ bias,
                                          float* __restrict__ C,
                                          int M, int N, int K, int bx, int by)
{
    constexpr int TM = 8, TN = 8;
    constexpr int THREADS = (BM / TM) * (BN / TN);     // 128
    __shared__ float  As[BK][BM];
    __shared__ float2 Bs[BK][BN];                      // duplicated (b, b)

    const int tid = threadIdx.x;
    const int bm  = bx * BM;
    const int bn  = by * BN;
    const int tx  = tid % (BN / TN);                   // 0..7
    const int ty  = tid / (BN / TN);                   // 0..15

    u64 acc[4][8];
#pragma unroll
    for (int i = 0; i < 4; i++)
#pragma unroll
        for (int j = 0; j < 8; j++) acc[i][j] = 0ull;

    constexpr int A_V4  = BM * BK / 4;
    constexpr int A_PER = A_V4 / THREADS;
    constexpr int B_V4  = BK * BN / 4;
    constexpr int B_PER = B_V4 / THREADS;
    static_assert(A_PER * THREADS == A_V4, "A tile");
    static_assert(B_PER * THREADS == B_V4, "B tile");

    for (int k0 = 0; k0 < K; k0 += BK) {
#pragma unroll
        for (int i = 0; i < A_PER; i++) {
            int v  = tid + i * THREADS;
            int r  = v / (BK / 4);
            int c4 = (v % (BK / 4)) * 4;
            int row = bm + r;
            float4 a = make_float4(0.f, 0.f, 0.f, 0.f);
            if (row < M)
                a = *(const float4*)&A[(long long)row * K + k0 + c4];
            As[c4 + 0][r] = a.x;
            As[c4 + 1][r] = a.y;
            As[c4 + 2][r] = a.z;
            As[c4 + 3][r] = a.w;
        }
#pragma unroll
        for (int i = 0; i < B_PER; i++) {
            int v  = tid + i * THREADS;
            int r  = v / (BN / 4);
            int c4 = (v % (BN / 4)) * 4;
            float4 b = *(const float4*)&B[(long long)(k0 + r) * N + bn + c4];
            Bs[r][c4 + 0] = make_float2(b.x, b.x);
            Bs[r][c4 + 1] = make_float2(b.y, b.y);
            Bs[r][c4 + 2] = make_float2(b.z, b.z);
            Bs[r][c4 + 3] = make_float2(b.w, b.w);
        }
        __syncthreads();

#pragma unroll 8
        for (int k = 0; k < BK; k++) {
            const u64* ap = (const u64*)&As[k][ty * TM];   // 4 M-pairs
            const u64* bp = (const u64*)&Bs[k][tx * TN];   // 8 dup'd cols
            u64 a2[4], b2[8];
#pragma unroll
            for (int i = 0; i < 4; i++) a2[i] = ap[i];
#pragma unroll
            for (int j = 0; j < 8; j++) b2[j] = bp[j];
#pragma unroll
            for (int i = 0; i < 4; i++)
#pragma unroll
                for (int j = 0; j < 8; j++) acc[i][j] = fma2(a2[i], b2[j], acc[i][j]);
        }
        __syncthreads();
    }

    float bcol[8];
    if (DOBIAS) {
#pragma unroll
        for (int j = 0; j < 8; j++) bcol[j] = bias[bn + tx * TN + j];
    }

#pragma unroll
    for (int i2 = 0; i2 < 4; i2++) {
        float2 p[8];
#pragma unroll
        for (int j = 0; j < 8; j++) p[j] = unpack2(acc[i2][j]);
#pragma unroll
        for (int rr = 0; rr < 2; rr++) {
            int row = bm + ty * TM + 2 * i2 + rr;
            if (row >= M) continue;
            float o[8];
#pragma unroll
            for (int j = 0; j < 8; j++) o[j] = rr ? p[j].y : p[j].x;
            if (DOSCALE) {
                float s = dinv[row];
#pragma unroll
                for (int j = 0; j < 8; j++) o[j] *= s;
            }
            if (DOBIAS) {
#pragma unroll
                for (int j = 0; j < 8; j++) o[j] += bcol[j];
            }
            long long offc = (long long)row * N + bn + tx * TN;
            *(float4*)&C[offc]     = make_float4(o[0], o[1], o[2], o[3]);
            *(float4*)&C[offc + 4] = make_float4(o[4], o[5], o[6], o[7]);
        }
    }
}

// ---------------------------------------------------------------------------
// fat: blocks [0, GB) = GEMM1 (hs1 = (x@W1)*dinv); blocks [GB,...) = CSR place.
// Both depend only on scan outputs -> run concurrently.
// ---------------------------------------------------------------------------
__global__ void __launch_bounds__(128) k_fat(
    const float* __restrict__ A, const float* __restrict__ B,
    const float* __restrict__ dinv, float* __restrict__ C,
    int M, int N, int K, int GB,
    const int* __restrict__ src, const int* __restrict__ dst,
    int* __restrict__ cur, int* __restrict__ srt, int E)
{
    if ((int)blockIdx.x < GB) {
        gemm_body<128, 64, 32, true, false>(A, B, dinv, nullptr, C, M, N, K, blockIdx.x, 0);
    } else {
        int i = (blockIdx.x - GB) * 128 + threadIdx.x;
        if (i < E) {
            int d = dst[i];
            int p = atomicAdd(&cur[d], 1);
            srt[p] = src[i];
        }
    }
}

// Layer-2 GEMM: out = hh2 @ W2 + b2
__global__ void __launch_bounds__(128) k_gemm2(
    const float* __restrict__ A, const float* __restrict__ B,
    const float* __restrict__ bias, float* __restrict__ C, int M, int N, int K)
{
    gemm_body<128, 64, 32, false, true>(A, B, nullptr, bias, C, M, N, K,
                                        blockIdx.x, blockIdx.y);
}

// ---------------------------------------------------------------------------
// CSR gather-aggregate over 64 features (16 float4 lanes per node).
// ---------------------------------------------------------------------------
template<bool BIAS, bool RELU, bool PRESCALE>
__global__ void k_gather64(const float4* __restrict__ hs,
                           const int*   __restrict__ off,
                           const int*   __restrict__ srt,
                           const float* __restrict__ dinv,
                           const float* __restrict__ bias,
                           float4* __restrict__ out, int N)
{
    const int tid  = threadIdx.x;
    const int node = blockIdx.x * 16 + (tid >> 4);
    const int nl   = tid & 15;
    if (node >= N) return;

    float4 acc = __ldg(&hs[node * 16 + nl]);    // self-loop term
    int       j   = __ldg(&off[node]);
    const int end = __ldg(&off[node + 1]);

    for (; j + 2 <= end; j += 2) {
        int s0 = __ldg(&srt[j]);
        int s1 = __ldg(&srt[j + 1]);
        float4 a = __ldg(&hs[s0 * 16 + nl]);
        float4 b = __ldg(&hs[s1 * 16 + nl]);
        acc.x += a.x + b.x;
        acc.y += a.y + b.y;
        acc.z += a.z + b.z;
        acc.w += a.w + b.w;
    }
    if (j < end) {
        int s = __ldg(&srt[j]);
        float4 a = __ldg(&hs[s * 16 + nl]);
        acc.x += a.x; acc.y += a.y; acc.z += a.z; acc.w += a.w;
    }

    const float s = __ldg(&dinv[node]);
    float4 r;
    r.x = acc.x * s; r.y = acc.y * s; r.z = acc.z * s; r.w = acc.w * s;
    if (BIAS) {
        float4 b = *(const float4*)&bias[nl * 4];
        r.x += b.x; r.y += b.y; r.z += b.z; r.w += b.w;
    }
    if (RELU) {
        r.x = fmaxf(r.x, 0.f); r.y = fmaxf(r.y, 0.f);
        r.z = fmaxf(r.z, 0.f); r.w = fmaxf(r.w, 0.f);
    }
    if (PRESCALE) { r.x *= s; r.y *= s; r.z *= s; r.w *= s; }
    out[node * 16 + nl] = r;
}

// ---------------------------------------------------------------------------
extern "C" void kernel_launch(void* const* d_in, const int* in_sizes, int n_in,
                              void* d_out, int out_size)
{
    const float* x   = (const float*)d_in[0];
    const int*   ei  = (const int*)d_in[1];      // int64 in reference -> int32 in harness
    const float* W1  = (const float*)d_in[2];
    const float* b1  = (const float*)d_in[3];
    const float* W2  = (const float*)d_in[4];
    const float* b2  = (const float*)d_in[5];
    float*       out = (float*)d_out;

    const int N = in_sizes[0] / FIN;     // 50000
    const int E = in_sizes[1] / 2;       // 1.6M
    const int* src = ei;
    const int* dst = ei + E;

    float *dinv, *hs1, *hh1, *hh2;
    int *hist, *off, *cur, *srt, *part, *poff;
    cudaGetSymbolAddress((void**)&dinv, g_dinv);
    cudaGetSymbolAddress((void**)&hs1,  g_hs1);
    cudaGetSymbolAddress((void**)&hh1,  g_hh1);
    cudaGetSymbolAddress((void**)&hh2,  g_hh2);
    cudaGetSymbolAddress((void**)&hist, g_hist);
    cudaGetSymbolAddress((void**)&off,  g_off);
    cudaGetSymbolAddress((void**)&cur,  g_cur);
    cudaGetSymbolAddress((void**)&srt,  g_srt);
    cudaGetSymbolAddress((void**)&part, g_part);
    cudaGetSymbolAddress((void**)&poff, g_poff);

    cudaMemsetAsync(hist, 0, N * sizeof(int));

    // --- degree histogram ---
    const bool can_v4 = (E % 4 == 0) && ((((unsigned long long)dst) & 15ull) == 0);
    if (can_v4) {
        int E4 = E / 4;
        k_hist4<<<(E4 + 255) / 256, 256>>>((const int4*)dst, hist, E4);
    } else {
        k_hist1<<<(E + 255) / 256, 256>>>(dst, hist, E);
    }

    // --- scan: offsets + dinv (3-phase parallel) ---
    const int NB = (N + 255) / 256;
    if (NB <= 256) {
        k_scanA<<<NB, 256>>>(hist, part, N);
        k_scanB<<<1, 256>>>(part, poff, NB);
        k_scanC<<<NB, 256>>>(hist, poff, off, cur, dinv, N);
    } else {
        k_scan1b<<<1, 1024>>>(hist, off, cur, dinv, N);
    }

    // --- fat: GEMM1 (hs1 = (x@W1)*dinv) overlapped with CSR place ---
    const int GB = (N + 127) / 128;
    const int PB = (E + 127) / 128;
    k_fat<<<GB + PB, 128>>>(x, W1, dinv, hs1, N, HID, FIN, GB,
                            src, dst, cur, srt, E);

    // hh1 = relu(dinv*(hs1_i + sum hs1_s) + b1) * dinv
    k_gather64<true, true, true><<<(N + 15) / 16, 256>>>((const float4*)hs1, off, srt,
                                                         dinv, b1, (float4*)hh1, N);
    // hh2 = dinv*(hh1_i + sum hh1_s) = A_hat @ h
    k_gather64<false, false, false><<<(N + 15) / 16, 256>>>((const float4*)hh1, off, srt,
                                                            dinv, nullptr, (float4*)hh2, N);
    // out = hh2 @ W2 + b2
    {
        dim3 grid(GB, FOUT / 64);
        k_gemm2<<<grid, 128>>>(hh2, W2, b2, out, N, FOUT, HID);
    }
}

// round 9
// speedup vs baseline: 1.5840x; 1.5840x over previous
#include <cuda_runtime.h>
#include <cuda_bf16.h>
#include <cstdint>

// Problem constants (GCN_71124658421835)
#define NMAX  50000
#define EMAX  1600000
#define FIN   256
#define HID   64
#define FOUT  128

// Scratch (no allocation allowed -> __device__ globals)
__device__ __align__(16) float g_dinv[NMAX];
__device__ __align__(16) float g_hs1 [NMAX * HID];     // x@W1 (RAW, unscaled)
__device__ __align__(16) float g_hh1 [NMAX * HID];     // relu(gcn1)*dinv
__device__ __align__(16) float g_hh2 [NMAX * HID];     // A_hat @ h
__device__ int g_hist[NMAX];
__device__ int g_off [NMAX + 1];
__device__ int g_cur [NMAX];
__device__ int g_srt [EMAX];                           // src sorted by dst (CSR adj)
__device__ int g_part[256];
__device__ int g_poff[256];

// ---------------------------------------------------------------------------
// GEMM body (R5 config: 256 threads, 8x4 tile, BK=16 — measured-good).
// C[row,col] = (A@B)[row,col] (+ bias[col] if DOBIAS)
// ---------------------------------------------------------------------------
template<int BM, int BN, int BK, int TM, int TN, bool DOBIAS>
__device__ __forceinline__ void gemm_body(const float* __restrict__ A,
                                          const float* __restrict__ B,
                                          const float* __restrict__ bias,
                                          float* __restrict__ C,
                                          int M, int N, int K, int bx, int by)
{
    constexpr int THREADS = (BM / TM) * (BN / TN);     // 256
    __shared__ float As[BK][BM];
    __shared__ float Bs[BK][BN];

    const int tid = threadIdx.x;
    const int bm  = bx * BM;
    const int bn  = by * BN;
    const int tx  = tid % (BN / TN);
    const int ty  = tid / (BN / TN);

    float acc[TM][TN];
#pragma unroll
    for (int i = 0; i < TM; i++)
#pragma unroll
        for (int j = 0; j < TN; j++) acc[i][j] = 0.0f;

    constexpr int A_V4  = BM * BK / 4;
    constexpr int A_PER = A_V4 / THREADS;
    constexpr int B_V4  = BK * BN / 4;
    constexpr int B_PER = B_V4 / THREADS;
    static_assert(A_PER * THREADS == A_V4, "A tile");
    static_assert(B_PER * THREADS == B_V4, "B tile");

    for (int k0 = 0; k0 < K; k0 += BK) {
#pragma unroll
        for (int i = 0; i < A_PER; i++) {
            int v  = tid + i * THREADS;
            int r  = v / (BK / 4);
            int c4 = (v % (BK / 4)) * 4;
            int row = bm + r;
            float4 a = make_float4(0.f, 0.f, 0.f, 0.f);
            if (row < M)
                a = *(const float4*)&A[(long long)row * K + k0 + c4];
            As[c4 + 0][r] = a.x;
            As[c4 + 1][r] = a.y;
            As[c4 + 2][r] = a.z;
            As[c4 + 3][r] = a.w;
        }
#pragma unroll
        for (int i = 0; i < B_PER; i++) {
            int v  = tid + i * THREADS;
            int r  = v / (BN / 4);
            int c4 = (v % (BN / 4)) * 4;
            *(float4*)&Bs[r][c4] = *(const float4*)&B[(long long)(k0 + r) * N + bn + c4];
        }
        __syncthreads();

#pragma unroll
        for (int k = 0; k < BK; k++) {
            float ra[TM], rb[TN];
#pragma unroll
            for (int i = 0; i < TM; i++) ra[i] = As[k][ty * TM + i];
#pragma unroll
            for (int j = 0; j < TN; j++) rb[j] = Bs[k][tx * TN + j];
#pragma unroll
            for (int i = 0; i < TM; i++)
#pragma unroll
                for (int j = 0; j < TN; j++) acc[i][j] += ra[i] * rb[j];
        }
        __syncthreads();
    }

    float4 bb = make_float4(0.f, 0.f, 0.f, 0.f);
    if (DOBIAS) bb = *(const float4*)&bias[bn + tx * TN];

#pragma unroll
    for (int i = 0; i < TM; i++) {
        int row = bm + ty * TM + i;
        if (row >= M) continue;
        float4 v;
        v.x = acc[i][0] + bb.x;
        v.y = acc[i][1] + bb.y;
        v.z = acc[i][2] + bb.z;
        v.w = acc[i][3] + bb.w;
        *(float4*)&C[(long long)row * N + bn + tx * TN] = v;
    }
}

// ---------------------------------------------------------------------------
// fat1: blocks [0, GB) = GEMM1 raw (x@W1 -> hs1); blocks [GB,...) = degree
// histogram (int4). 256 threads. GEMM needs no dinv -> fully independent.
// ---------------------------------------------------------------------------
__global__ void __launch_bounds__(256) k_fat1(
    const float* __restrict__ A, const float* __restrict__ B, float* __restrict__ C,
    int M, int N, int K, int GB,
    const int4* __restrict__ dst4, int* __restrict__ hist, int E4)
{
    if ((int)blockIdx.x < GB) {
        gemm_body<128, 64, 16, 8, 4, false>(A, B, nullptr, C, M, N, K, blockIdx.x, 0);
    } else {
        int i = (blockIdx.x - GB) * 256 + threadIdx.x;
        if (i < E4) {
            int4 d = __ldg(&dst4[i]);
            atomicAdd(&hist[d.x], 1);
            atomicAdd(&hist[d.y], 1);
            atomicAdd(&hist[d.z], 1);
            atomicAdd(&hist[d.w], 1);
        }
    }
}

__global__ void k_hist1(const int* __restrict__ dst, int* hist, int E) {
    int i = blockIdx.x * blockDim.x + threadIdx.x;
    if (i < E) atomicAdd(&hist[dst[i]], 1);
}

// ---------------------------------------------------------------------------
// 3-phase parallel exclusive scan over hist (N <= 65536), emits off/cur/dinv.
// ---------------------------------------------------------------------------
__global__ void k_scanA(const int* __restrict__ hist, int* __restrict__ part, int n) {
    __shared__ int s[256];
    int t = threadIdx.x, i = blockIdx.x * 256 + t;
    s[t] = (i < n) ? hist[i] : 0;
    __syncthreads();
    for (int d = 128; d > 0; d >>= 1) {
        if (t < d) s[t] += s[t + d];
        __syncthreads();
    }
    if (t == 0) part[blockIdx.x] = s[0];
}

__global__ void k_scanB(const int* __restrict__ part, int* __restrict__ poff, int nb) {
    __shared__ int s[256];
    int t = threadIdx.x;
    int v = (t < nb) ? part[t] : 0;
    s[t] = v;
    __syncthreads();
    for (int d = 1; d < 256; d <<= 1) {
        int x = (t >= d) ? s[t - d] : 0;
        __syncthreads();
        s[t] += x;
        __syncthreads();
    }
    if (t < nb) poff[t] = s[t] - v;          // exclusive
}

__global__ void k_scanC(const int* __restrict__ hist, const int* __restrict__ poff,
                        int* __restrict__ off, int* __restrict__ cur,
                        float* __restrict__ dinv, int n)
{
    __shared__ int s[256];
    int t = threadIdx.x, i = blockIdx.x * 256 + t;
    int v = (i < n) ? hist[i] : 0;
    s[t] = v;
    __syncthreads();
    for (int d = 1; d < 256; d <<= 1) {
        int x = (t >= d) ? s[t - d] : 0;
        __syncthreads();
        s[t] += x;
        __syncthreads();
    }
    int base = poff[blockIdx.x];
    int excl = base + s[t] - v;
    if (i < n) {
        off[i]  = excl;
        cur[i]  = excl;
        dinv[i] = rsqrtf((float)v + 1.0f);   // +1 self loop
    }
    if (i == n - 1) off[n] = excl + v;
}

// Fallback single-block scan (only if N > 65536)
__global__ void k_scan1b(const int* __restrict__ hist, int* __restrict__ off,
                         int* __restrict__ cur, float* __restrict__ dinv, int n)
{
    __shared__ int sums[1024];
    const int t = threadIdx.x;
    const int chunk = (n + 1023) >> 10;
    const int lo = t * chunk;
    const int hi = min(lo + chunk, n);
    int s = 0;
    for (int i = lo; i < hi; i++) s += hist[i];
    sums[t] = s;
    __syncthreads();
    for (int d = 1; d < 1024; d <<= 1) {
        int v = (t >= d) ? sums[t - d] : 0;
        __syncthreads();
        sums[t] += v;
        __syncthreads();
    }
    int run = (t == 0) ? 0 : sums[t - 1];
    for (int i = lo; i < hi; i++) {
        int c = hist[i];
        off[i] = run; cur[i] = run;
        dinv[i] = rsqrtf((float)c + 1.0f);
        run += c;
    }
    if (t == 1023) off[n] = sums[1023];
}

__global__ void k_place(const int* __restrict__ src,
                        const int* __restrict__ dst,
                        int* cur, int* __restrict__ srt, int E)
{
    int i = blockIdx.x * blockDim.x + threadIdx.x;
    if (i < E) {
        int d = dst[i];
        int p = atomicAdd(&cur[d], 1);
        srt[p] = src[i];
    }
}

// ---------------------------------------------------------------------------
// CSR gather-aggregate over 64 features (16 float4 lanes/node, 16 nodes/block).
// SRCSCALE: input rows are RAW; each contribution (incl. self) scaled by
//           dinv[src] at load time.   Else: input rows already prescaled.
// r = dinv[node]*acc ; +bias ; relu ; *dinv[node] (prescale for next layer)
// Edge loop unrolled x4 for MLP against L2 latency.
// ---------------------------------------------------------------------------
template<bool SRCSCALE, bool BIAS, bool RELU, bool PRESCALE>
__global__ void k_gather64(const float4* __restrict__ hs,
                           const int*   __restrict__ off,
                           const int*   __restrict__ srt,
                           const float* __restrict__ dinv,
                           const float* __restrict__ bias,
                           float4* __restrict__ out, int N)
{
    const int tid  = threadIdx.x;
    const int node = blockIdx.x * 16 + (tid >> 4);
    const int nl   = tid & 15;
    if (node >= N) return;

    const float sn = __ldg(&dinv[node]);

    float4 self = __ldg(&hs[node * 16 + nl]);
    float4 acc;
    if (SRCSCALE) {
        acc.x = self.x * sn; acc.y = self.y * sn;
        acc.z = self.z * sn; acc.w = self.w * sn;
    } else {
        acc = self;
    }

    int       j   = __ldg(&off[node]);
    const int end = __ldg(&off[node + 1]);

    for (; j + 4 <= end; j += 4) {
        int s0 = __ldg(&srt[j + 0]);
        int s1 = __ldg(&srt[j + 1]);
        int s2 = __ldg(&srt[j + 2]);
        int s3 = __ldg(&srt[j + 3]);
        float4 v0 = __ldg(&hs[s0 * 16 + nl]);
        float4 v1 = __ldg(&hs[s1 * 16 + nl]);
        float4 v2 = __ldg(&hs[s2 * 16 + nl]);
        float4 v3 = __ldg(&hs[s3 * 16 + nl]);
        if (SRCSCALE) {
            float d0 = __ldg(&dinv[s0]);
            float d1 = __ldg(&dinv[s1]);
            float d2 = __ldg(&dinv[s2]);
            float d3 = __ldg(&dinv[s3]);
            acc.x = fmaf(v0.x, d0, acc.x); acc.y = fmaf(v0.y, d0, acc.y);
            acc.z = fmaf(v0.z, d0, acc.z); acc.w = fmaf(v0.w, d0, acc.w);
            acc.x = fmaf(v1.x, d1, acc.x); acc.y = fmaf(v1.y, d1, acc.y);
            acc.z = fmaf(v1.z, d1, acc.z); acc.w = fmaf(v1.w, d1, acc.w);
            acc.x = fmaf(v2.x, d2, acc.x); acc.y = fmaf(v2.y, d2, acc.y);
            acc.z = fmaf(v2.z, d2, acc.z); acc.w = fmaf(v2.w, d2, acc.w);
            acc.x = fmaf(v3.x, d3, acc.x); acc.y = fmaf(v3.y, d3, acc.y);
            acc.z = fmaf(v3.z, d3, acc.z); acc.w = fmaf(v3.w, d3, acc.w);
        } else {
            acc.x += (v0.x + v1.x) + (v2.x + v3.x);
            acc.y += (v0.y + v1.y) + (v2.y + v3.y);
            acc.z += (v0.z + v1.z) + (v2.z + v3.z);
            acc.w += (v0.w + v1.w) + (v2.w + v3.w);
        }
    }
    for (; j < end; j++) {
        int s = __ldg(&srt[j]);
        float4 v = __ldg(&hs[s * 16 + nl]);
        if (SRCSCALE) {
            float d = __ldg(&dinv[s]);
            acc.x = fmaf(v.x, d, acc.x); acc.y = fmaf(v.y, d, acc.y);
            acc.z = fmaf(v.z, d, acc.z); acc.w = fmaf(v.w, d, acc.w);
        } else {
            acc.x += v.x; acc.y += v.y; acc.z += v.z; acc.w += v.w;
        }
    }

    float4 r;
    r.x = acc.x * sn; r.y = acc.y * sn; r.z = acc.z * sn; r.w = acc.w * sn;
    if (BIAS) {
        float4 b = *(const float4*)&bias[nl * 4];
        r.x += b.x; r.y += b.y; r.z += b.z; r.w += b.w;
    }
    if (RELU) {
        r.x = fmaxf(r.x, 0.f); r.y = fmaxf(r.y, 0.f);
        r.z = fmaxf(r.z, 0.f); r.w = fmaxf(r.w, 0.f);
    }
    if (PRESCALE) { r.x *= sn; r.y *= sn; r.z *= sn; r.w *= sn; }
    out[node * 16 + nl] = r;
}

// Layer-2 GEMM: out = hh2 @ W2 + b2
__global__ void __launch_bounds__(256) k_gemm2(
    const float* __restrict__ A, const float* __restrict__ B,
    const float* __restrict__ bias, float* __restrict__ C, int M, int N, int K)
{
    gemm_body<128, 64, 16, 8, 4, true>(A, B, bias, C, M, N, K, blockIdx.x, blockIdx.y);
}

// ---------------------------------------------------------------------------
extern "C" void kernel_launch(void* const* d_in, const int* in_sizes, int n_in,
                              void* d_out, int out_size)
{
    const float* x   = (const float*)d_in[0];
    const int*   ei  = (const int*)d_in[1];      // int64 in reference -> int32 in harness
    const float* W1  = (const float*)d_in[2];
    const float* b1  = (const float*)d_in[3];
    const float* W2  = (const float*)d_in[4];
    const float* b2  = (const float*)d_in[5];
    float*       out = (float*)d_out;

    const int N = in_sizes[0] / FIN;     // 50000
    const int E = in_sizes[1] / 2;       // 1.6M
    const int* src = ei;
    const int* dst = ei + E;

    float *dinv, *hs1, *hh1, *hh2;
    int *hist, *off, *cur, *srt, *part, *poff;
    cudaGetSymbolAddress((void**)&dinv, g_dinv);
    cudaGetSymbolAddress((void**)&hs1,  g_hs1);
    cudaGetSymbolAddress((void**)&hh1,  g_hh1);
    cudaGetSymbolAddress((void**)&hh2,  g_hh2);
    cudaGetSymbolAddress((void**)&hist, g_hist);
    cudaGetSymbolAddress((void**)&off,  g_off);
    cudaGetSymbolAddress((void**)&cur,  g_cur);
    cudaGetSymbolAddress((void**)&srt,  g_srt);
    cudaGetSymbolAddress((void**)&part, g_part);
    cudaGetSymbolAddress((void**)&poff, g_poff);

    cudaMemsetAsync(hist, 0, N * sizeof(int));

    const int GB = (N + 127) / 128;                      // GEMM1 M-blocks (391)
    const bool can_v4 = (E % 4 == 0) && ((((unsigned long long)dst) & 15ull) == 0);

    // --- fat1: GEMM1 raw (x@W1 -> hs1) overlapped with degree histogram ---
    if (can_v4) {
        const int E4 = E / 4;
        const int HB = (E4 + 255) / 256;
        k_fat1<<<GB + HB, 256>>>(x, W1, hs1, N, HID, FIN, GB,
                                 (const int4*)dst, hist, E4);
    } else {
        k_hist1<<<(E + 255) / 256, 256>>>(dst, hist, E);
        k_fat1<<<GB, 256>>>(x, W1, hs1, N, HID, FIN, GB, nullptr, hist, 0);
    }

    // --- scan: offsets + dinv (3-phase parallel) ---
    const int NB = (N + 255) / 256;
    if (NB <= 256) {
        k_scanA<<<NB, 256>>>(hist, part, N);
        k_scanB<<<1, 256>>>(part, poff, NB);
        k_scanC<<<NB, 256>>>(hist, poff, off, cur, dinv, N);
    } else {
        k_scan1b<<<1, 1024>>>(hist, off, cur, dinv, N);
    }

    // --- CSR place ---
    k_place<<<(E + 255) / 256, 256>>>(src, dst, cur, srt, E);

    // hh1 = relu(dinv_n*(sum_{s in nbr+self} hs1raw[s]*dinv_s) + b1) * dinv_n
    k_gather64<true, true, true, true><<<(N + 15) / 16, 256>>>(
        (const float4*)hs1, off, srt, dinv, b1, (float4*)hh1, N);
    // hh2 = dinv_n*(hh1_n + sum hh1_s)
    k_gather64<false, false, false, false><<<(N + 15) / 16, 256>>>(
        (const float4*)hh1, off, srt, dinv, nullptr, (float4*)hh2, N);
    // out = hh2 @ W2 + b2
    {
        dim3 grid(GB, FOUT / 64);
        k_gemm2<<<grid, 256>>>(hh2, W2, b2, out, N, FOUT, HID);
    }
}

// round 11
// speedup vs baseline: 1.6073x; 1.0147x over previous
#include <cuda_runtime.h>
#include <cuda_bf16.h>
#include <cstdint>

// Problem constants (GCN_71124658421835)
#define NMAX  50000
#define EMAX  1600000
#define FIN   256
#define HID   64
#define FOUT  128

// Scratch (no allocation allowed -> __device__ globals)
__device__ __align__(16) float g_dinv[NMAX];
__device__ __align__(16) float g_hs1 [NMAX * HID];     // x@W1 (RAW, unscaled)
__device__ __align__(16) float g_hh1 [NMAX * HID];     // relu(gcn1)*dinv
__device__ __align__(16) float g_hh2 [NMAX * HID];     // A_hat @ h
__device__ int g_hist[NMAX];
__device__ int g_off [NMAX + 1];
__device__ int g_rank[EMAX];                           // rank of edge within dst bucket
__device__ int g_srt [EMAX];                           // src sorted by dst (CSR adj)
__device__ int g_part[256];

// ---------------------------------------------------------------------------
// GEMM body (measured-good config: 256 threads, 8x4 tile, BK=16).
// C[row,col] = (A@B)[row,col] (+ bias[col] if DOBIAS)
// ---------------------------------------------------------------------------
template<int BM, int BN, int BK, int TM, int TN, bool DOBIAS>
__device__ __forceinline__ void gemm_body(const float* __restrict__ A,
                                          const float* __restrict__ B,
                                          const float* __restrict__ bias,
                                          float* __restrict__ C,
                                          int M, int N, int K, int bx, int by)
{
    constexpr int THREADS = (BM / TM) * (BN / TN);     // 256
    __shared__ float As[BK][BM];
    __shared__ float Bs[BK][BN];

    const int tid = threadIdx.x;
    const int bm  = bx * BM;
    const int bn  = by * BN;
    const int tx  = tid % (BN / TN);
    const int ty  = tid / (BN / TN);

    float acc[TM][TN];
#pragma unroll
    for (int i = 0; i < TM; i++)
#pragma unroll
        for (int j = 0; j < TN; j++) acc[i][j] = 0.0f;

    constexpr int A_V4  = BM * BK / 4;
    constexpr int A_PER = A_V4 / THREADS;
    constexpr int B_V4  = BK * BN / 4;
    constexpr int B_PER = B_V4 / THREADS;
    static_assert(A_PER * THREADS == A_V4, "A tile");
    static_assert(B_PER * THREADS == B_V4, "B tile");

    for (int k0 = 0; k0 < K; k0 += BK) {
#pragma unroll
        for (int i = 0; i < A_PER; i++) {
            int v  = tid + i * THREADS;
            int r  = v / (BK / 4);
            int c4 = (v % (BK / 4)) * 4;
            int row = bm + r;
            float4 a = make_float4(0.f, 0.f, 0.f, 0.f);
            if (row < M)
                a = *(const float4*)&A[(long long)row * K + k0 + c4];
            As[c4 + 0][r] = a.x;
            As[c4 + 1][r] = a.y;
            As[c4 + 2][r] = a.z;
            As[c4 + 3][r] = a.w;
        }
#pragma unroll
        for (int i = 0; i < B_PER; i++) {
            int v  = tid + i * THREADS;
            int r  = v / (BN / 4);
            int c4 = (v % (BN / 4)) * 4;
            *(float4*)&Bs[r][c4] = *(const float4*)&B[(long long)(k0 + r) * N + bn + c4];
        }
        __syncthreads();

#pragma unroll
        for (int k = 0; k < BK; k++) {
            float ra[TM], rb[TN];
#pragma unroll
            for (int i = 0; i < TM; i++) ra[i] = As[k][ty * TM + i];
#pragma unroll
            for (int j = 0; j < TN; j++) rb[j] = Bs[k][tx * TN + j];
#pragma unroll
            for (int i = 0; i < TM; i++)
#pragma unroll
                for (int j = 0; j < TN; j++) acc[i][j] += ra[i] * rb[j];
        }
        __syncthreads();
    }

    float4 bb = make_float4(0.f, 0.f, 0.f, 0.f);
    if (DOBIAS) bb = *(const float4*)&bias[bn + tx * TN];

#pragma unroll
    for (int i = 0; i < TM; i++) {
        int row = bm + ty * TM + i;
        if (row >= M) continue;
        float4 v;
        v.x = acc[i][0] + bb.x;
        v.y = acc[i][1] + bb.y;
        v.z = acc[i][2] + bb.z;
        v.w = acc[i][3] + bb.w;
        *(float4*)&C[(long long)row * N + bn + tx * TN] = v;
    }
}

// ---------------------------------------------------------------------------
// fat1: blocks [0, GB) = GEMM1 raw (x@W1 -> hs1); blocks [GB,...) = degree
// histogram + per-edge bucket rank (int4). GEMM needs no dinv -> independent.
// ---------------------------------------------------------------------------
__global__ void __launch_bounds__(256) k_fat1(
    const float* __restrict__ A, const float* __restrict__ B, float* __restrict__ C,
    int M, int N, int K, int GB,
    const int4* __restrict__ dst4, int* __restrict__ hist,
    int4* __restrict__ rank4, int E4)
{
    if ((int)blockIdx.x < GB) {
        gemm_body<128, 64, 16, 8, 4, false>(A, B, nullptr, C, M, N, K, blockIdx.x, 0);
    } else {
        int i = (blockIdx.x - GB) * 256 + threadIdx.x;
        if (i < E4) {
            int4 d = __ldg(&dst4[i]);
            int4 r;
            r.x = atomicAdd(&hist[d.x], 1);
            r.y = atomicAdd(&hist[d.y], 1);
            r.z = atomicAdd(&hist[d.z], 1);
            r.w = atomicAdd(&hist[d.w], 1);
            rank4[i] = r;
        }
    }
}

__global__ void k_hist1(const int* __restrict__ dst, int* hist,
                        int* __restrict__ rank, int E) {
    int i = blockIdx.x * blockDim.x + threadIdx.x;
    if (i < E) rank[i] = atomicAdd(&hist[dst[i]], 1);
}

// ---------------------------------------------------------------------------
// 2-phase parallel exclusive scan over hist (N <= 65536), emits off + dinv.
// ---------------------------------------------------------------------------
__global__ void k_scanA(const int* __restrict__ hist, int* __restrict__ part, int n) {
    __shared__ int s[256];
    int t = threadIdx.x, i = blockIdx.x * 256 + t;
    s[t] = (i < n) ? hist[i] : 0;
    __syncthreads();
    for (int d = 128; d > 0; d >>= 1) {
        if (t < d) s[t] += s[t + d];
        __syncthreads();
    }
    if (t == 0) part[blockIdx.x] = s[0];
}

// scanC: each block redundantly scans the block-partials (<=256 ints) to get
// its base, then scans its own 256 hist entries. Emits off + dinv.
__global__ void k_scanC(const int* __restrict__ hist, const int* __restrict__ part,
                        int* __restrict__ off, float* __restrict__ dinv, int n, int nb)
{
    __shared__ int sp[256];
    __shared__ int s[256];
    int t = threadIdx.x, i = blockIdx.x * 256 + t;

    // scan partials
    int pv = (t < nb) ? part[t] : 0;
    sp[t] = pv;
    __syncthreads();
    for (int d = 1; d < 256; d <<= 1) {
        int x = (t >= d) ? sp[t - d] : 0;
        __syncthreads();
        sp[t] += x;
        __syncthreads();
    }
    int base = (blockIdx.x > 0) ? sp[blockIdx.x - 1] : 0;

    // scan own chunk
    int v = (i < n) ? hist[i] : 0;
    s[t] = v;
    __syncthreads();
    for (int d = 1; d < 256; d <<= 1) {
        int x = (t >= d) ? s[t - d] : 0;
        __syncthreads();
        s[t] += x;
        __syncthreads();
    }
    int excl = base + s[t] - v;
    if (i < n) {
        off[i]  = excl;
        dinv[i] = rsqrtf((float)v + 1.0f);   // +1 self loop
    }
    if (i == n - 1) off[n] = excl + v;
}

// Fallback single-block scan (only if N > 65536)
__global__ void k_scan1b(const int* __restrict__ hist, int* __restrict__ off,
                         float* __restrict__ dinv, int n)
{
    __shared__ int sums[1024];
    const int t = threadIdx.x;
    const int chunk = (n + 1023) >> 10;
    const int lo = t * chunk;
    const int hi = min(lo + chunk, n);
    int s = 0;
    for (int i = lo; i < hi; i++) s += hist[i];
    sums[t] = s;
    __syncthreads();
    for (int d = 1; d < 1024; d <<= 1) {
        int v = (t >= d) ? sums[t - d] : 0;
        __syncthreads();
        sums[t] += v;
        __syncthreads();
    }
    int run = (t == 0) ? 0 : sums[t - 1];
    for (int i = lo; i < hi; i++) {
        int c = hist[i];
        off[i] = run;
        dinv[i] = rsqrtf((float)c + 1.0f);
        run += c;
    }
    if (t == 1023) off[n] = sums[1023];
}

// ---------------------------------------------------------------------------
// place (atomic-free): srt[off[dst] + rank] = src
// ---------------------------------------------------------------------------
__global__ void k_place2(const int* __restrict__ src, const int* __restrict__ dst,
                         const int* __restrict__ rank, const int* __restrict__ off,
                         int* __restrict__ srt, int E)
{
    int i = blockIdx.x * blockDim.x + threadIdx.x;
    if (i < E)
        srt[__ldg(&off[dst[i]]) + rank[i]] = src[i];
}

// ---------------------------------------------------------------------------
// CSR gather-aggregate over 64 features (16 float4 lanes/node, 16 nodes/block).
// SRCSCALE: input rows are RAW; each contribution (incl. self) scaled by
//           dinv[src] at load time.   Else: input rows already prescaled.
// r = dinv[node]*acc ; +bias ; relu ; *dinv[node] (prescale for next layer)
// ---------------------------------------------------------------------------
template<bool SRCSCALE, bool BIAS, bool RELU, bool PRESCALE>
__global__ void k_gather64(const float4* __restrict__ hs,
                           const int*   __restrict__ off,
                           const int*   __restrict__ srt,
                           const float* __restrict__ dinv,
                           const float* __restrict__ bias,
                           float4* __restrict__ out, int N)
{
    const int tid  = threadIdx.x;
    const int node = blockIdx.x * 16 + (tid >> 4);
    const int nl   = tid & 15;
    if (node >= N) return;

    const float sn = __ldg(&dinv[node]);

    float4 self = __ldg(&hs[node * 16 + nl]);
    float4 acc;
    if (SRCSCALE) {
        acc.x = self.x * sn; acc.y = self.y * sn;
        acc.z = self.z * sn; acc.w = self.w * sn;
    } else {
        acc = self;
    }

    int       j   = __ldg(&off[node]);
    const int end = __ldg(&off[node + 1]);

    for (; j + 4 <= end; j += 4) {
        int s0 = __ldg(&srt[j + 0]);
        int s1 = __ldg(&srt[j + 1]);
        int s2 = __ldg(&srt[j + 2]);
        int s3 = __ldg(&srt[j + 3]);
        float4 v0 = __ldg(&hs[s0 * 16 + nl]);
        float4 v1 = __ldg(&hs[s1 * 16 + nl]);
        float4 v2 = __ldg(&hs[s2 * 16 + nl]);
        float4 v3 = __ldg(&hs[s3 * 16 + nl]);
        if (SRCSCALE) {
            float d0 = __ldg(&dinv[s0]);
            float d1 = __ldg(&dinv[s1]);
            float d2 = __ldg(&dinv[s2]);
            float d3 = __ldg(&dinv[s3]);
            acc.x = fmaf(v0.x, d0, acc.x); acc.y = fmaf(v0.y, d0, acc.y);
            acc.z = fmaf(v0.z, d0, acc.z); acc.w = fmaf(v0.w, d0, acc.w);
            acc.x = fmaf(v1.x, d1, acc.x); acc.y = fmaf(v1.y, d1, acc.y);
            acc.z = fmaf(v1.z, d1, acc.z); acc.w = fmaf(v1.w, d1, acc.w);
            acc.x = fmaf(v2.x, d2, acc.x); acc.y = fmaf(v2.y, d2, acc.y);
            acc.z = fmaf(v2.z, d2, acc.z); acc.w = fmaf(v2.w, d2, acc.w);
            acc.x = fmaf(v3.x, d3, acc.x); acc.y = fmaf(v3.y, d3, acc.y);
            acc.z = fmaf(v3.z, d3, acc.z); acc.w = fmaf(v3.w, d3, acc.w);
        } else {
            acc.x += (v0.x + v1.x) + (v2.x + v3.x);
            acc.y += (v0.y + v1.y) + (v2.y + v3.y);
            acc.z += (v0.z + v1.z) + (v2.z + v3.z);
            acc.w += (v0.w + v1.w) + (v2.w + v3.w);
        }
    }
    for (; j < end; j++) {
        int s = __ldg(&srt[j]);
        float4 v = __ldg(&hs[s * 16 + nl]);
        if (SRCSCALE) {
            float d = __ldg(&dinv[s]);
            acc.x = fmaf(v.x, d, acc.x); acc.y = fmaf(v.y, d, acc.y);
            acc.z = fmaf(v.z, d, acc.z); acc.w = fmaf(v.w, d, acc.w);
        } else {
            acc.x += v.x; acc.y += v.y; acc.z += v.z; acc.w += v.w;
        }
    }

    float4 r;
    r.x = acc.x * sn; r.y = acc.y * sn; r.z = acc.z * sn; r.w = acc.w * sn;
    if (BIAS) {
        float4 b = *(const float4*)&bias[nl * 4];
        r.x += b.x; r.y += b.y; r.z += b.z; r.w += b.w;
    }
    if (RELU) {
        r.x = fmaxf(r.x, 0.f); r.y = fmaxf(r.y, 0.f);
        r.z = fmaxf(r.z, 0.f); r.w = fmaxf(r.w, 0.f);
    }
    if (PRESCALE) { r.x *= sn; r.y *= sn; r.z *= sn; r.w *= sn; }
    out[node * 16 + nl] = r;
}

// Layer-2 GEMM: out = hh2 @ W2 + b2
__global__ void __launch_bounds__(256) k_gemm2(
    const float* __restrict__ A, const float* __restrict__ B,
    const float* __restrict__ bias, float* __restrict__ C, int M, int N, int K)
{
    gemm_body<128, 64, 16, 8, 4, true>(A, B, bias, C, M, N, K, blockIdx.x, blockIdx.y);
}

// ---------------------------------------------------------------------------
extern "C" void kernel_launch(void* const* d_in, const int* in_sizes, int n_in,
                              void* d_out, int out_size)
{
    const float* x   = (const float*)d_in[0];
    const int*   ei  = (const int*)d_in[1];      // int64 in reference -> int32 in harness
    const float* W1  = (const float*)d_in[2];
    const float* b1  = (const float*)d_in[3];
    const float* W2  = (const float*)d_in[4];
    const float* b2  = (const float*)d_in[5];
    float*       out = (float*)d_out;

    const int N = in_sizes[0] / FIN;     // 50000
    const int E = in_sizes[1] / 2;       // 1.6M
    const int* src = ei;
    const int* dst = ei + E;

    float *dinv, *hs1, *hh1, *hh2;
    int *hist, *off, *rank, *srt, *part;
    cudaGetSymbolAddress((void**)&dinv, g_dinv);
    cudaGetSymbolAddress((void**)&hs1,  g_hs1);
    cudaGetSymbolAddress((void**)&hh1,  g_hh1);
    cudaGetSymbolAddress((void**)&hh2,  g_hh2);
    cudaGetSymbolAddress((void**)&hist, g_hist);
    cudaGetSymbolAddress((void**)&off,  g_off);
    cudaGetSymbolAddress((void**)&rank, g_rank);
    cudaGetSymbolAddress((void**)&srt,  g_srt);
    cudaGetSymbolAddress((void**)&part, g_part);

    cudaMemsetAsync(hist, 0, N * sizeof(int));

    const int GB = (N + 127) / 128;                      // GEMM1 M-blocks (391)
    const bool can_v4 = (E % 4 == 0) && ((((unsigned long long)dst) & 15ull) == 0);

    // --- fat1: GEMM1 raw (x@W1 -> hs1) overlapped with histogram + rank ---
    if (can_v4) {
        const int E4 = E / 4;
        const int HB = (E4 + 255) / 256;
        k_fat1<<<GB + HB, 256>>>(x, W1, hs1, N, HID, FIN, GB,
                                 (const int4*)dst, hist, (int4*)rank, E4);
    } else {
        k_hist1<<<(E + 255) / 256, 256>>>(dst, hist, rank, E);
        k_fat1<<<GB, 256>>>(x, W1, hs1, N, HID, FIN, GB, nullptr, hist, nullptr, 0);
    }

    // --- scan: offsets + dinv (2-phase parallel) ---
    const int NB = (N + 255) / 256;
    if (NB <= 256) {
        k_scanA<<<NB, 256>>>(hist, part, N);
        k_scanC<<<NB, 256>>>(hist, part, off, dinv, N, NB);
    } else {
        k_scan1b<<<1, 1024>>>(hist, off, dinv, N);
    }

    // --- CSR place (atomic-free) ---
    k_place2<<<(E + 255) / 256, 256>>>(src, dst, rank, off, srt, E);

    // hh1 = relu(dinv_n*(sum_{s in nbr+self} hs1raw[s]*dinv_s) + b1) * dinv_n
    k_gather64<true, true, true, true><<<(N + 15) / 16, 256>>>(
        (const float4*)hs1, off, srt, dinv, b1, (float4*)hh1, N);
    // hh2 = dinv_n*(hh1_n + sum hh1_s)
    k_gather64<false, false, false, false><<<(N + 15) / 16, 256>>>(
        (const float4*)hh1, off, srt, dinv, nullptr, (float4*)hh2, N);
    // out = hh2 @ W2 + b2
    {
        dim3 grid(GB, FOUT / 64);
        k_gemm2<<<grid, 256>>>(hh2, W2, b2, out, N, FOUT, HID);
    }
}

// round 15
// speedup vs baseline: 1.6227x; 1.0096x over previous
#include <cuda_runtime.h>
#include <cuda_bf16.h>
#include <cstdint>

// Problem constants (GCN_71124658421835)
#define NMAX  50000
#define EMAX  1600000
#define FIN   256
#define HID   64
#define FOUT  128

// Scratch (no allocation allowed -> __device__ globals)
__device__ __align__(16) float g_dinv[NMAX];
__device__ __align__(16) float g_hs1 [NMAX * HID];     // x@W1 (RAW, unscaled)
__device__ __align__(16) float g_hh1 [NMAX * HID];     // relu(gcn1)*dinv
__device__ int g_hist[NMAX];
__device__ int g_off [NMAX + 1];
__device__ int g_rank[EMAX];                           // rank of edge within dst bucket
__device__ int g_srt [EMAX];                           // src sorted by dst (CSR adj)
__device__ int g_part[256];

// ---------------------------------------------------------------------------
// GEMM body (measured-good config: 256 threads, 8x4 tile, BK=16).
// ---------------------------------------------------------------------------
template<int BM, int BN, int BK, int TM, int TN>
__device__ __forceinline__ void gemm_body(const float* __restrict__ A,
                                          const float* __restrict__ B,
                                          float* __restrict__ C,
                                          int M, int N, int K, int bx, int by)
{
    constexpr int THREADS = (BM / TM) * (BN / TN);     // 256
    __shared__ float As[BK][BM];
    __shared__ float Bs[BK][BN];

    const int tid = threadIdx.x;
    const int bm  = bx * BM;
    const int bn  = by * BN;
    const int tx  = tid % (BN / TN);
    const int ty  = tid / (BN / TN);

    float acc[TM][TN];
#pragma unroll
    for (int i = 0; i < TM; i++)
#pragma unroll
        for (int j = 0; j < TN; j++) acc[i][j] = 0.0f;

    constexpr int A_V4  = BM * BK / 4;
    constexpr int A_PER = A_V4 / THREADS;
    constexpr int B_V4  = BK * BN / 4;
    constexpr int B_PER = B_V4 / THREADS;
    static_assert(A_PER * THREADS == A_V4, "A tile");
    static_assert(B_PER * THREADS == B_V4, "B tile");

    for (int k0 = 0; k0 < K; k0 += BK) {
#pragma unroll
        for (int i = 0; i < A_PER; i++) {
            int v  = tid + i * THREADS;
            int r  = v / (BK / 4);
            int c4 = (v % (BK / 4)) * 4;
            int row = bm + r;
            float4 a = make_float4(0.f, 0.f, 0.f, 0.f);
            if (row < M)
                a = *(const float4*)&A[(long long)row * K + k0 + c4];
            As[c4 + 0][r] = a.x;
            As[c4 + 1][r] = a.y;
            As[c4 + 2][r] = a.z;
            As[c4 + 3][r] = a.w;
        }
#pragma unroll
        for (int i = 0; i < B_PER; i++) {
            int v  = tid + i * THREADS;
            int r  = v / (BN / 4);
            int c4 = (v % (BN / 4)) * 4;
            *(float4*)&Bs[r][c4] = *(const float4*)&B[(long long)(k0 + r) * N + bn + c4];
        }
        __syncthreads();

#pragma unroll
        for (int k = 0; k < BK; k++) {
            float ra[TM], rb[TN];
#pragma unroll
            for (int i = 0; i < TM; i++) ra[i] = As[k][ty * TM + i];
#pragma unroll
            for (int j = 0; j < TN; j++) rb[j] = Bs[k][tx * TN + j];
#pragma unroll
            for (int i = 0; i < TM; i++)
#pragma unroll
                for (int j = 0; j < TN; j++) acc[i][j] += ra[i] * rb[j];
        }
        __syncthreads();
    }

#pragma unroll
    for (int i = 0; i < TM; i++) {
        int row = bm + ty * TM + i;
        if (row >= M) continue;
        float4 v;
        v.x = acc[i][0];
        v.y = acc[i][1];
        v.z = acc[i][2];
        v.w = acc[i][3];
        *(float4*)&C[(long long)row * N + bn + tx * TN] = v;
    }
}

// ---------------------------------------------------------------------------
// fat1: blocks [0, GB) = GEMM1 raw (x@W1 -> hs1); blocks [GB,...) = degree
// histogram + per-edge bucket rank (int4). GEMM needs no dinv -> independent.
// ---------------------------------------------------------------------------
__global__ void __launch_bounds__(256) k_fat1(
    const float* __restrict__ A, const float* __restrict__ B, float* __restrict__ C,
    int M, int N, int K, int GB,
    const int4* __restrict__ dst4, int* __restrict__ hist,
    int4* __restrict__ rank4, int E4)
{
    if ((int)blockIdx.x < GB) {
        gemm_body<128, 64, 16, 8, 4>(A, B, C, M, N, K, blockIdx.x, 0);
    } else {
        int i = (blockIdx.x - GB) * 256 + threadIdx.x;
        if (i < E4) {
            int4 d = __ldg(&dst4[i]);
            int4 r;
            r.x = atomicAdd(&hist[d.x], 1);
            r.y = atomicAdd(&hist[d.y], 1);
            r.z = atomicAdd(&hist[d.z], 1);
            r.w = atomicAdd(&hist[d.w], 1);
            rank4[i] = r;
        }
    }
}

__global__ void k_hist1(const int* __restrict__ dst, int* hist,
                        int* __restrict__ rank, int E) {
    int i = blockIdx.x * blockDim.x + threadIdx.x;
    if (i < E) rank[i] = atomicAdd(&hist[dst[i]], 1);
}

// ---------------------------------------------------------------------------
// 2-phase parallel exclusive scan over hist (N <= 65536), emits off + dinv.
// ---------------------------------------------------------------------------
__global__ void k_scanA(const int* __restrict__ hist, int* __restrict__ part, int n) {
    __shared__ int s[256];
    int t = threadIdx.x, i = blockIdx.x * 256 + t;
    s[t] = (i < n) ? hist[i] : 0;
    __syncthreads();
    for (int d = 128; d > 0; d >>= 1) {
        if (t < d) s[t] += s[t + d];
        __syncthreads();
    }
    if (t == 0) part[blockIdx.x] = s[0];
}

__global__ void k_scanC(const int* __restrict__ hist, const int* __restrict__ part,
                        int* __restrict__ off, float* __restrict__ dinv, int n, int nb)
{
    __shared__ int sp[256];
    __shared__ int s[256];
    int t = threadIdx.x, i = blockIdx.x * 256 + t;

    int pv = (t < nb) ? part[t] : 0;
    sp[t] = pv;
    __syncthreads();
    for (int d = 1; d < 256; d <<= 1) {
        int x = (t >= d) ? sp[t - d] : 0;
        __syncthreads();
        sp[t] += x;
        __syncthreads();
    }
    int base = (blockIdx.x > 0) ? sp[blockIdx.x - 1] : 0;

    int v = (i < n) ? hist[i] : 0;
    s[t] = v;
    __syncthreads();
    for (int d = 1; d < 256; d <<= 1) {
        int x = (t >= d) ? s[t - d] : 0;
        __syncthreads();
        s[t] += x;
        __syncthreads();
    }
    int excl = base + s[t] - v;
    if (i < n) {
        off[i]  = excl;
        dinv[i] = rsqrtf((float)v + 1.0f);   // +1 self loop
    }
    if (i == n - 1) off[n] = excl + v;
}

__global__ void k_scan1b(const int* __restrict__ hist, int* __restrict__ off,
                         float* __restrict__ dinv, int n)
{
    __shared__ int sums[1024];
    const int t = threadIdx.x;
    const int chunk = (n + 1023) >> 10;
    const int lo = t * chunk;
    const int hi = min(lo + chunk, n);
    int s = 0;
    for (int i = lo; i < hi; i++) s += hist[i];
    sums[t] = s;
    __syncthreads();
    for (int d = 1; d < 1024; d <<= 1) {
        int v = (t >= d) ? sums[t - d] : 0;
        __syncthreads();
        sums[t] += v;
        __syncthreads();
    }
    int run = (t == 0) ? 0 : sums[t - 1];
    for (int i = lo; i < hi; i++) {
        int c = hist[i];
        off[i] = run;
        dinv[i] = rsqrtf((float)c + 1.0f);
        run += c;
    }
    if (t == 1023) off[n] = sums[1023];
}

// ---------------------------------------------------------------------------
// place (atomic-free): srt[off[dst] + rank] = src
// ---------------------------------------------------------------------------
__global__ void k_place2(const int* __restrict__ src, const int* __restrict__ dst,
                         const int* __restrict__ rank, const int* __restrict__ off,
                         int* __restrict__ srt, int E)
{
    int i = blockIdx.x * blockDim.x + threadIdx.x;
    if (i < E)
        srt[__ldg(&off[dst[i]]) + rank[i]] = src[i];
}

// ---------------------------------------------------------------------------
// gather1: 64-feature CSR gather with src-side dinv scaling + bias/relu/prescale
// hh1[n] = relu(dinv_n * sum_{s in nbr+self} hs1raw[s]*dinv_s + b1) * dinv_n
// ---------------------------------------------------------------------------
__global__ void k_gather1(const float4* __restrict__ hs,
                          const int*   __restrict__ off,
                          const int*   __restrict__ srt,
                          const float* __restrict__ dinv,
                          const float* __restrict__ bias,
                          float4* __restrict__ out, int N)
{
    const int tid  = threadIdx.x;
    const int node = blockIdx.x * 16 + (tid >> 4);
    const int nl   = tid & 15;
    if (node >= N) return;

    const float sn = __ldg(&dinv[node]);

    float4 self = __ldg(&hs[node * 16 + nl]);
    float4 acc;
    acc.x = self.x * sn; acc.y = self.y * sn;
    acc.z = self.z * sn; acc.w = self.w * sn;

    int       j   = __ldg(&off[node]);
    const int end = __ldg(&off[node + 1]);

    for (; j + 4 <= end; j += 4) {
        int s0 = __ldg(&srt[j + 0]);
        int s1 = __ldg(&srt[j + 1]);
        int s2 = __ldg(&srt[j + 2]);
        int s3 = __ldg(&srt[j + 3]);
        float4 v0 = __ldg(&hs[s0 * 16 + nl]);
        float4 v1 = __ldg(&hs[s1 * 16 + nl]);
        float4 v2 = __ldg(&hs[s2 * 16 + nl]);
        float4 v3 = __ldg(&hs[s3 * 16 + nl]);
        float d0 = __ldg(&dinv[s0]);
        float d1 = __ldg(&dinv[s1]);
        float d2 = __ldg(&dinv[s2]);
        float d3 = __ldg(&dinv[s3]);
        acc.x = fmaf(v0.x, d0, acc.x); acc.y = fmaf(v0.y, d0, acc.y);
        acc.z = fmaf(v0.z, d0, acc.z); acc.w = fmaf(v0.w, d0, acc.w);
        acc.x = fmaf(v1.x, d1, acc.x); acc.y = fmaf(v1.y, d1, acc.y);
        acc.z = fmaf(v1.z, d1, acc.z); acc.w = fmaf(v1.w, d1, acc.w);
        acc.x = fmaf(v2.x, d2, acc.x); acc.y = fmaf(v2.y, d2, acc.y);
        acc.z = fmaf(v2.z, d2, acc.z); acc.w = fmaf(v2.w, d2, acc.w);
        acc.x = fmaf(v3.x, d3, acc.x); acc.y = fmaf(v3.y, d3, acc.y);
        acc.z = fmaf(v3.z, d3, acc.z); acc.w = fmaf(v3.w, d3, acc.w);
    }
    for (; j < end; j++) {
        int s = __ldg(&srt[j]);
        float4 v = __ldg(&hs[s * 16 + nl]);
        float d = __ldg(&dinv[s]);
        acc.x = fmaf(v.x, d, acc.x); acc.y = fmaf(v.y, d, acc.y);
        acc.z = fmaf(v.z, d, acc.z); acc.w = fmaf(v.w, d, acc.w);
    }

    float4 r;
    r.x = acc.x * sn; r.y = acc.y * sn; r.z = acc.z * sn; r.w = acc.w * sn;
    float4 b = *(const float4*)&bias[nl * 4];
    r.x += b.x; r.y += b.y; r.z += b.z; r.w += b.w;
    r.x = fmaxf(r.x, 0.f); r.y = fmaxf(r.y, 0.f);
    r.z = fmaxf(r.z, 0.f); r.w = fmaxf(r.w, 0.f);
    r.x *= sn; r.y *= sn; r.z *= sn; r.w *= sn;
    out[node * 16 + nl] = r;
}

// ---------------------------------------------------------------------------
// Fused gather2 + GEMM2:
//   per block (128 rows, all 128 output cols):
//     phase 1: Ag[r][k] = dinv_n * (hh1[n,k] + sum_{s} hh1[s,k])   (SMEM)
//     phase 2: out[n, :] = Ag[r, :] @ W2 + b2
// 256 threads. Dynamic SMEM: Ag[128][68] + Bs[64][128].
// ---------------------------------------------------------------------------
#define AG_LD 68
#define G2_SMEM ((128 * AG_LD + 64 * 128) * 4)

__global__ void __launch_bounds__(256) k_gemm2f(
    const float4* __restrict__ hh1,
    const int*    __restrict__ off,
    const int*    __restrict__ srt,
    const float*  __restrict__ dinv,
    const float*  __restrict__ W2,     // [64][128] row-major
    const float*  __restrict__ b2,     // [128]
    float* __restrict__ out, int N)
{
    extern __shared__ float smem[];
    float* Ag = smem;                   // [128][AG_LD]
    float* Bs = smem + 128 * AG_LD;     // [64][128]

    const int tid = threadIdx.x;
    const int bm  = blockIdx.x * 128;

    // ---- phase 1: gather 128 rows into Ag ----
    {
        const int nl   = tid & 15;       // float4 lane (k4)
        const int sub  = tid >> 4;       // 0..15: node-within-pass
        for (int p = 0; p < 8; p++) {
            int lr   = p * 16 + sub;     // local row 0..127
            int node = bm + lr;
            float4 r = make_float4(0.f, 0.f, 0.f, 0.f);
            if (node < N) {
                float sn = __ldg(&dinv[node]);
                float4 acc = __ldg(&hh1[node * 16 + nl]);   // self (prescaled)
                int       j   = __ldg(&off[node]);
                const int end = __ldg(&off[node + 1]);
                for (; j + 4 <= end; j += 4) {
                    int s0 = __ldg(&srt[j + 0]);
                    int s1 = __ldg(&srt[j + 1]);
                    int s2 = __ldg(&srt[j + 2]);
                    int s3 = __ldg(&srt[j + 3]);
                    float4 v0 = __ldg(&hh1[s0 * 16 + nl]);
                    float4 v1 = __ldg(&hh1[s1 * 16 + nl]);
                    float4 v2 = __ldg(&hh1[s2 * 16 + nl]);
                    float4 v3 = __ldg(&hh1[s3 * 16 + nl]);
                    acc.x += (v0.x + v1.x) + (v2.x + v3.x);
                    acc.y += (v0.y + v1.y) + (v2.y + v3.y);
                    acc.z += (v0.z + v1.z) + (v2.z + v3.z);
                    acc.w += (v0.w + v1.w) + (v2.w + v3.w);
                }
                for (; j < end; j++) {
                    int s = __ldg(&srt[j]);
                    float4 v = __ldg(&hh1[s * 16 + nl]);
                    acc.x += v.x; acc.y += v.y; acc.z += v.z; acc.w += v.w;
                }
                r.x = acc.x * sn; r.y = acc.y * sn;
                r.z = acc.z * sn; r.w = acc.w * sn;
            }
            *(float4*)&Ag[lr * AG_LD + nl * 4] = r;
        }
    }

    // ---- load W2 into Bs (flat copy: 64*128 floats) ----
    {
        const float4* w4 = (const float4*)W2;
        float4*       s4 = (float4*)Bs;
        for (int i = tid; i < 64 * 128 / 4; i += 256)
            s4[i] = __ldg(&w4[i]);
    }
    __syncthreads();

    // ---- phase 2: FFMA tile. tx = tid%16 (8 cols each), ty = tid/16 (8 rows each)
    const int tx = tid & 15;
    const int ty = tid >> 4;

    float acc[8][8];
#pragma unroll
    for (int i = 0; i < 8; i++)
#pragma unroll
        for (int j = 0; j < 8; j++) acc[i][j] = 0.0f;

#pragma unroll 4
    for (int k = 0; k < 64; k++) {
        float ra[8], rb[8];
#pragma unroll
        for (int i = 0; i < 8; i++) ra[i] = Ag[(ty * 8 + i) * AG_LD + k];
#pragma unroll
        for (int j = 0; j < 8; j++) rb[j] = Bs[k * 128 + tx * 8 + j];
#pragma unroll
        for (int i = 0; i < 8; i++)
#pragma unroll
            for (int j = 0; j < 8; j++) acc[i][j] += ra[i] * rb[j];
    }

    float4 bb0 = *(const float4*)&b2[tx * 8];
    float4 bb1 = *(const float4*)&b2[tx * 8 + 4];

#pragma unroll
    for (int i = 0; i < 8; i++) {
        int row = bm + ty * 8 + i;
        if (row >= N) continue;
        float4 v0, v1;
        v0.x = acc[i][0] + bb0.x; v0.y = acc[i][1] + bb0.y;
        v0.z = acc[i][2] + bb0.z; v0.w = acc[i][3] + bb0.w;
        v1.x = acc[i][4] + bb1.x; v1.y = acc[i][5] + bb1.y;
        v1.z = acc[i][6] + bb1.z; v1.w = acc[i][7] + bb1.w;
        long long o = (long long)row * 128 + tx * 8;
        *(float4*)&out[o]     = v0;
        *(float4*)&out[o + 4] = v1;
    }
}

// ---------------------------------------------------------------------------
extern "C" void kernel_launch(void* const* d_in, const int* in_sizes, int n_in,
                              void* d_out, int out_size)
{
    const float* x   = (const float*)d_in[0];
    const int*   ei  = (const int*)d_in[1];      // int64 in reference -> int32 in harness
    const float* W1  = (const float*)d_in[2];
    const float* b1  = (const float*)d_in[3];
    const float* W2  = (const float*)d_in[4];
    const float* b2  = (const float*)d_in[5];
    float*       out = (float*)d_out;

    const int N = in_sizes[0] / FIN;     // 50000
    const int E = in_sizes[1] / 2;       // 1.6M
    const int* src = ei;
    const int* dst = ei + E;

    float *dinv, *hs1, *hh1;
    int *hist, *off, *rank, *srt, *part;
    cudaGetSymbolAddress((void**)&dinv, g_dinv);
    cudaGetSymbolAddress((void**)&hs1,  g_hs1);
    cudaGetSymbolAddress((void**)&hh1,  g_hh1);
    cudaGetSymbolAddress((void**)&hist, g_hist);
    cudaGetSymbolAddress((void**)&off,  g_off);
    cudaGetSymbolAddress((void**)&rank, g_rank);
    cudaGetSymbolAddress((void**)&srt,  g_srt);
    cudaGetSymbolAddress((void**)&part, g_part);

    cudaFuncSetAttribute(k_gemm2f, cudaFuncAttributeMaxDynamicSharedMemorySize,
                         G2_SMEM);

    cudaMemsetAsync(hist, 0, N * sizeof(int));

    const int GB = (N + 127) / 128;                      // GEMM1 M-blocks (391)
    const bool can_v4 = (E % 4 == 0) && ((((unsigned long long)dst) & 15ull) == 0);

    // --- fat1: GEMM1 raw (x@W1 -> hs1) overlapped with histogram + rank ---
    if (can_v4) {
        const int E4 = E / 4;
        const int HB = (E4 + 255) / 256;
        k_fat1<<<GB + HB, 256>>>(x, W1, hs1, N, HID, FIN, GB,
                                 (const int4*)dst, hist, (int4*)rank, E4);
    } else {
        k_hist1<<<(E + 255) / 256, 256>>>(dst, hist, rank, E);
        k_fat1<<<GB, 256>>>(x, W1, hs1, N, HID, FIN, GB, nullptr, hist, nullptr, 0);
    }

    // --- scan: offsets + dinv (2-phase parallel) ---
    const int NB = (N + 255) / 256;
    if (NB <= 256) {
        k_scanA<<<NB, 256>>>(hist, part, N);
        k_scanC<<<NB, 256>>>(hist, part, off, dinv, N, NB);
    } else {
        k_scan1b<<<1, 1024>>>(hist, off, dinv, N);
    }

    // --- CSR place (atomic-free) ---
    k_place2<<<(E + 255) / 256, 256>>>(src, dst, rank, off, srt, E);

    // hh1 = relu(dinv_n*(sum hs1raw[s]*dinv_s) + b1) * dinv_n
    k_gather1<<<(N + 15) / 16, 256>>>((const float4*)hs1, off, srt, dinv, b1,
                                      (float4*)hh1, N);

    // out = (A_hat @ hh1) @ W2 + b2   (fused gather + GEMM)
    k_gemm2f<<<GB, 256, G2_SMEM>>>((const float4*)hh1, off, srt, dinv,
                                   W2, b2, out, N);
}